// round 1
// baseline (speedup 1.0000x reference)
#include <cuda_runtime.h>
#include <math.h>
#include <float.h>

// ---------------- problem constants ----------------
#define SEQ  2048
#define BSZ  2
#define EMB  1024
#define NH   16
#define HD   64
#define BH   (BSZ*NH)          // 32
#define MROWS (SEQ*BSZ)        // 4096 flattened (s,b) rows

// ---------------- scratch (static device allocations; no cudaMalloc) ------
__device__ float g_q[(size_t)BH*SEQ*HD];        // 16 MB   [bh][s][d]
__device__ float g_k[(size_t)BH*SEQ*HD];        // 16 MB
__device__ float g_v[(size_t)BH*SEQ*HD];        // 16 MB
__device__ float g_attn[(size_t)BH*SEQ*SEQ];    // 512 MB  [bh][q][k]
__device__ float g_ctx[(size_t)MROWS*EMB];      // 16 MB   [m=(s*B+b)][e=h*64+d]
__device__ float g_ow[(size_t)EMB*EMB];         // 4 MB    sampled output weight

// ---------------- elementwise: sampled Bayesian weight --------------------
__global__ void ow_kernel(const float* __restrict__ mean,
                          const float* __restrict__ lgstd,
                          const float* __restrict__ eps)
{
    int i = blockIdx.x * blockDim.x + threadIdx.x;
    if (i < EMB * EMB)
        g_ow[i] = mean[i] + eps[i] * expf(lgstd[i]);
}

// ---------------- tiled SGEMM, C = A * B^T  (A[m,k], B[n,k]) --------------
// MODE 0: plain C[m*ldc+n]
// MODE 1: qkv epilogue: v=(acc+bias[n])*scale, scatter to [bh][s][d]
template<int BM,int BN,int BK,int TM,int TN,int MODE>
__global__ void sgemm_nt(const float* __restrict__ A, const float* __restrict__ B,
                         float* __restrict__ C,
                         int K, int lda, int ldb, int ldc,
                         size_t sA, size_t sB, size_t sC,
                         const float* __restrict__ bias, float scale)
{
    constexpr int THREADS = (BM/TM)*(BN/TN);
    A += (size_t)blockIdx.z * sA;
    B += (size_t)blockIdx.z * sB;
    C += (size_t)blockIdx.z * sC;

    __shared__ float As[BK][BM];
    __shared__ float Bs[BK][BN];

    const int tid    = threadIdx.x;
    const int blockM = blockIdx.y * BM;
    const int blockN = blockIdx.x * BN;
    const int tRow   = tid / (BN/TN);
    const int tCol   = tid % (BN/TN);

    float acc[TM][TN];
    #pragma unroll
    for (int i = 0; i < TM; i++)
        #pragma unroll
        for (int j = 0; j < TN; j++) acc[i][j] = 0.f;

    const int arow = tid / (BK/4);
    const int acol = tid % (BK/4);
    constexpr int APASS = THREADS / (BK/4);

    for (int kt = 0; kt < K; kt += BK) {
        #pragma unroll
        for (int r = 0; r < BM; r += APASS) {
            float4 t = *(const float4*)&A[(size_t)(blockM + arow + r)*lda + kt + acol*4];
            As[acol*4+0][arow+r] = t.x;
            As[acol*4+1][arow+r] = t.y;
            As[acol*4+2][arow+r] = t.z;
            As[acol*4+3][arow+r] = t.w;
        }
        #pragma unroll
        for (int r = 0; r < BN; r += APASS) {
            float4 t = *(const float4*)&B[(size_t)(blockN + arow + r)*ldb + kt + acol*4];
            Bs[acol*4+0][arow+r] = t.x;
            Bs[acol*4+1][arow+r] = t.y;
            Bs[acol*4+2][arow+r] = t.z;
            Bs[acol*4+3][arow+r] = t.w;
        }
        __syncthreads();

        #pragma unroll
        for (int k = 0; k < BK; k++) {
            float ra[TM], rb[TN];
            #pragma unroll
            for (int i = 0; i < TM; i++) ra[i] = As[k][tRow*TM + i];
            #pragma unroll
            for (int j = 0; j < TN; j++) rb[j] = Bs[k][tCol*TN + j];
            #pragma unroll
            for (int i = 0; i < TM; i++)
                #pragma unroll
                for (int j = 0; j < TN; j++)
                    acc[i][j] = fmaf(ra[i], rb[j], acc[i][j]);
        }
        __syncthreads();
    }

    #pragma unroll
    for (int i = 0; i < TM; i++) {
        const int m = blockM + tRow*TM + i;
        #pragma unroll
        for (int j = 0; j < TN; j++) {
            const int n = blockN + tCol*TN + j;
            float v = acc[i][j];
            if (MODE == 1) {
                v = (v + bias[n]) * scale;
                const int b = m & (BSZ-1);
                const int s = m >> 1;        // BSZ == 2
                const int h = n >> 6;        // HD == 64
                const int d = n & (HD-1);
                C[((size_t)(b*NH + h)*SEQ + s)*HD + d] = v;
            } else {
                C[(size_t)m*ldc + n] = v;
            }
        }
    }
}

// ---------------- tiled SGEMM, C = A * B  (A[m,k], B[k,n]) ----------------
// MODE 0: plain; MODE 1: ctx scatter to [m*BSZ+b][h*HD+n] (bh = blockIdx.z)
template<int BM,int BN,int BK,int TM,int TN,int MODE>
__global__ void sgemm_nn(const float* __restrict__ A, const float* __restrict__ B,
                         float* __restrict__ C,
                         int K, int lda, int ldb, int ldc,
                         size_t sA, size_t sB, size_t sC)
{
    constexpr int THREADS = (BM/TM)*(BN/TN);
    const int bh = blockIdx.z;
    A += (size_t)bh * sA;
    B += (size_t)bh * sB;
    C += (size_t)bh * sC;

    __shared__ float As[BK][BM];
    __shared__ float Bs[BK][BN];

    const int tid    = threadIdx.x;
    const int blockM = blockIdx.y * BM;
    const int blockN = blockIdx.x * BN;
    const int tRow   = tid / (BN/TN);
    const int tCol   = tid % (BN/TN);

    float acc[TM][TN];
    #pragma unroll
    for (int i = 0; i < TM; i++)
        #pragma unroll
        for (int j = 0; j < TN; j++) acc[i][j] = 0.f;

    const int arow = tid / (BK/4);
    const int acol = tid % (BK/4);
    constexpr int APASS = THREADS / (BK/4);

    const int brow = tid / (BN/4);
    const int bcol = tid % (BN/4);
    constexpr int BPASS = THREADS / (BN/4);

    for (int kt = 0; kt < K; kt += BK) {
        #pragma unroll
        for (int r = 0; r < BM; r += APASS) {
            float4 t = *(const float4*)&A[(size_t)(blockM + arow + r)*lda + kt + acol*4];
            As[acol*4+0][arow+r] = t.x;
            As[acol*4+1][arow+r] = t.y;
            As[acol*4+2][arow+r] = t.z;
            As[acol*4+3][arow+r] = t.w;
        }
        #pragma unroll
        for (int r = 0; r < BK; r += BPASS) {
            float4 t = *(const float4*)&B[(size_t)(kt + brow + r)*ldb + blockN + bcol*4];
            *(float4*)&Bs[brow + r][bcol*4] = t;
        }
        __syncthreads();

        #pragma unroll
        for (int k = 0; k < BK; k++) {
            float ra[TM], rb[TN];
            #pragma unroll
            for (int i = 0; i < TM; i++) ra[i] = As[k][tRow*TM + i];
            #pragma unroll
            for (int j = 0; j < TN; j++) rb[j] = Bs[k][tCol*TN + j];
            #pragma unroll
            for (int i = 0; i < TM; i++)
                #pragma unroll
                for (int j = 0; j < TN; j++)
                    acc[i][j] = fmaf(ra[i], rb[j], acc[i][j]);
        }
        __syncthreads();
    }

    #pragma unroll
    for (int i = 0; i < TM; i++) {
        const int m = blockM + tRow*TM + i;
        #pragma unroll
        for (int j = 0; j < TN; j++) {
            const int n = blockN + tCol*TN + j;
            if (MODE == 1) {
                const int b = bh >> 4;   // NH == 16
                const int h = bh & 15;
                C[(size_t)(m*BSZ + b)*EMB + h*HD + n] = acc[i][j];
            } else {
                C[(size_t)m*ldc + n] = acc[i][j];
            }
        }
    }
}

// ---------------- row softmax (row length SEQ, 256 threads/row) -----------
__device__ __forceinline__ float warpMax(float v) {
    #pragma unroll
    for (int o = 16; o; o >>= 1) v = fmaxf(v, __shfl_xor_sync(0xffffffffu, v, o));
    return v;
}
__device__ __forceinline__ float warpSum(float v) {
    #pragma unroll
    for (int o = 16; o; o >>= 1) v += __shfl_xor_sync(0xffffffffu, v, o);
    return v;
}

__global__ void softmax_kernel(float* __restrict__ attn)
{
    constexpr int T   = 256;
    constexpr int PER = SEQ / T;     // 8
    __shared__ float sm[8];

    const size_t row = blockIdx.x;
    float* p = attn + row * (size_t)SEQ;
    const int tid  = threadIdx.x;
    const int lane = tid & 31;
    const int wid  = tid >> 5;

    float x[PER];
    #pragma unroll
    for (int i = 0; i < PER; i++) x[i] = p[tid + i*T];

    float m = -FLT_MAX;
    #pragma unroll
    for (int i = 0; i < PER; i++) m = fmaxf(m, x[i]);
    m = warpMax(m);
    if (lane == 0) sm[wid] = m;
    __syncthreads();
    if (wid == 0) {
        float t = (lane < 8) ? sm[lane] : -FLT_MAX;
        t = warpMax(t);
        if (lane == 0) sm[0] = t;
    }
    __syncthreads();
    const float rowMax = sm[0];
    __syncthreads();

    float s = 0.f;
    #pragma unroll
    for (int i = 0; i < PER; i++) { x[i] = __expf(x[i] - rowMax); s += x[i]; }
    s = warpSum(s);
    if (lane == 0) sm[wid] = s;
    __syncthreads();
    if (wid == 0) {
        float t = (lane < 8) ? sm[lane] : 0.f;
        t = warpSum(t);
        if (lane == 0) sm[0] = t;
    }
    __syncthreads();
    const float inv = 1.f / sm[0];

    #pragma unroll
    for (int i = 0; i < PER; i++) p[tid + i*T] = x[i] * inv;
}

// ---------------- head-average of attn -> avg_attn ------------------------
__global__ void avg_kernel(float* __restrict__ out)
{
    const size_t total4 = (size_t)BSZ * SEQ * SEQ / 4;
    size_t idx = (size_t)blockIdx.x * blockDim.x + threadIdx.x;
    if (idx >= total4) return;
    const size_t e = idx * 4;
    const int    k = (int)(e % SEQ);
    const size_t t = e / SEQ;
    const int    q = (int)(t % SEQ);
    const int    b = (int)(t / SEQ);

    float4 s = make_float4(0.f, 0.f, 0.f, 0.f);
    #pragma unroll
    for (int h = 0; h < NH; h++) {
        const float4 v = *(const float4*)&g_attn[((size_t)(b*NH + h)*SEQ + q)*SEQ + k];
        s.x += v.x; s.y += v.y; s.z += v.z; s.w += v.w;
    }
    const float inv = 1.f / NH;
    s.x *= inv; s.y *= inv; s.z *= inv; s.w *= inv;
    *(float4*)&out[e] = s;
}

// ---------------- launch ---------------------------------------------------
extern "C" void kernel_launch(void* const* d_in, const int* in_sizes, int n_in,
                              void* d_out, int out_size)
{
    const float* query   = (const float*)d_in[0];
    const float* key     = (const float*)d_in[1];
    const float* value   = (const float*)d_in[2];
    const float* q_w     = (const float*)d_in[3];
    const float* q_b     = (const float*)d_in[4];
    const float* k_w     = (const float*)d_in[5];
    const float* k_b     = (const float*)d_in[6];
    const float* v_w     = (const float*)d_in[7];
    const float* v_b     = (const float*)d_in[8];
    const float* ow_mean = (const float*)d_in[9];
    const float* ow_lg   = (const float*)d_in[10];
    const float* eps     = (const float*)d_in[11];

    float* out_main = (float*)d_out;                       // [S,B,E]
    float* out_avg  = out_main + (size_t)MROWS * EMB;      // [B,S,S]

    float *q_p, *k_p, *v_p, *attn_p, *ctx_p, *ow_p;
    cudaGetSymbolAddress((void**)&q_p,    g_q);
    cudaGetSymbolAddress((void**)&k_p,    g_k);
    cudaGetSymbolAddress((void**)&v_p,    g_v);
    cudaGetSymbolAddress((void**)&attn_p, g_attn);
    cudaGetSymbolAddress((void**)&ctx_p,  g_ctx);
    cudaGetSymbolAddress((void**)&ow_p,   g_ow);

    // 1. sampled output weight
    ow_kernel<<<(EMB*EMB + 255)/256, 256>>>(ow_mean, ow_lg, eps);

    // 2. Q/K/V projections ([4096,1024] x [1024,1024]^T), scatter to [bh][s][d]
    const dim3 gProj(EMB/128, MROWS/128, 1);
    sgemm_nt<128,128,16,8,8,1><<<gProj, 256>>>(query, q_w, q_p, EMB, EMB, EMB, 0,
                                               0, 0, 0, q_b, 0.125f);
    sgemm_nt<128,128,16,8,8,1><<<gProj, 256>>>(key,   k_w, k_p, EMB, EMB, EMB, 0,
                                               0, 0, 0, k_b, 1.0f);
    sgemm_nt<128,128,16,8,8,1><<<gProj, 256>>>(value, v_w, v_p, EMB, EMB, EMB, 0,
                                               0, 0, 0, v_b, 1.0f);

    // 3. scores = Q K^T, batched over bh
    const dim3 gScore(SEQ/128, SEQ/128, BH);
    sgemm_nt<128,128,16,8,8,0><<<gScore, 256>>>(q_p, k_p, attn_p, HD, HD, HD, SEQ,
                                                (size_t)SEQ*HD, (size_t)SEQ*HD,
                                                (size_t)SEQ*SEQ, nullptr, 1.0f);

    // 4. softmax rows (in place)
    softmax_kernel<<<BH*SEQ, 256>>>(attn_p);

    // 5. ctx = attn @ V, batched, scattered into [m][e] layout
    const dim3 gCtx(1, SEQ/128, BH);
    sgemm_nn<128,64,16,8,4,1><<<gCtx, 256>>>(attn_p, v_p, ctx_p, SEQ, SEQ, HD, 0,
                                             (size_t)SEQ*SEQ, (size_t)SEQ*HD, 0);

    // 6. avg_attn over heads
    {
        const size_t total4 = (size_t)BSZ*SEQ*SEQ/4;
        avg_kernel<<<(unsigned)((total4 + 255)/256), 256>>>(out_avg);
    }

    // 7. out = ctx @ o_w^T
    sgemm_nt<128,128,16,8,8,0><<<gProj, 256>>>(ctx_p, ow_p, out_main, EMB, EMB, EMB,
                                               EMB, 0, 0, 0, nullptr, 1.0f);
}

// round 2
// speedup vs baseline: 1.2957x; 1.2957x over previous
#include <cuda_runtime.h>
#include <math.h>
#include <float.h>

// ---------------- problem constants ----------------
#define SEQ  2048
#define BSZ  2
#define EMB  1024
#define NH   16
#define HD   64
#define BH   (BSZ*NH)          // 32
#define MROWS (SEQ*BSZ)        // 4096

// ---------------- scratch ----------------
__device__ float g_q[(size_t)BH*SEQ*HD];
__device__ float g_k[(size_t)BH*SEQ*HD];
__device__ float g_v[(size_t)BH*SEQ*HD];
__device__ float g_attn[(size_t)BH*SEQ*SEQ];    // 512 MB
__device__ float g_ctx[(size_t)MROWS*EMB];
__device__ float g_ow[(size_t)EMB*EMB];

// ---------------- f32x2 packed FMA helpers ----------------
using u64 = unsigned long long;

__device__ __forceinline__ void fma2(u64 &c, u64 a, u64 b) {
    asm("fma.rn.f32x2 %0, %1, %2, %0;" : "+l"(c) : "l"(a), "l"(b));
}
__device__ __forceinline__ float hsum2(u64 v) {
    return __uint_as_float((unsigned)v) + __uint_as_float((unsigned)(v >> 32));
}

// ---------------- sampled Bayesian output weight ----------------
__global__ void ow_kernel(const float* __restrict__ mean,
                          const float* __restrict__ lgstd,
                          const float* __restrict__ eps)
{
    int i = blockIdx.x * blockDim.x + threadIdx.x;
    if (i < EMB * EMB)
        g_ow[i] = mean[i] + eps[i] * expf(lgstd[i]);
}

// =====================================================================
// GEMM NT:  C = A * B^T.  A[m,k], B[n,k].  128x128 tile, BK=16.
// Inner loop: k-parity packed f32x2 FMAs (FFMA2), accumulators hold
// (even-k, odd-k) partial sums, reduced horizontally at the end.
// MODE 0: C[m*ldc+n]   MODE 1: qkv epilogue (bias+scale, scatter [bh][s][d])
// =====================================================================
template<int MODE>
__global__ __launch_bounds__(256, 1)
void gemm_nt_f2(const float* __restrict__ A, const float* __restrict__ B,
                float* __restrict__ C, int K, int lda, int ldb, int ldc,
                size_t sA, size_t sB, size_t sC,
                const float* __restrict__ bias, float scale)
{
    constexpr int BM = 128, BN = 128, BK = 16, BK2 = 8, BMP = 134;
    A += (size_t)blockIdx.z * sA;
    B += (size_t)blockIdx.z * sB;
    C += (size_t)blockIdx.z * sC;

    __shared__ float2 As2[2][BK2][BMP];   // [k2][m] = {A[m][2k2], A[m][2k2+1]}
    __shared__ float2 Bs2[2][BK2][BMP];

    const int tid  = threadIdx.x;
    const int tCol = tid & 15;           // n-group
    const int tRow = tid >> 4;           // m-group
    const int blockM = blockIdx.y * BM;
    const int blockN = blockIdx.x * BN;

    // loaders: 512 float4 per tile per matrix -> 2 per thread
    const int lm = tid >> 2;             // row 0..63 (and +64)
    const int lc = tid & 3;              // float4 column within BK
    const float* Aload = A + (size_t)(blockM + lm) * lda + lc * 4;
    const float* Bload = B + (size_t)(blockN + lm) * ldb + lc * 4;

    u64 acc[8][8];
    #pragma unroll
    for (int i = 0; i < 8; i++)
        #pragma unroll
        for (int j = 0; j < 8; j++) acc[i][j] = 0ull;

    const int ntiles = K / BK;
    float4 fa0, fa1, fb0, fb1;

    fa0 = *(const float4*)(Aload);
    fa1 = *(const float4*)(Aload + (size_t)64 * lda);
    fb0 = *(const float4*)(Bload);
    fb1 = *(const float4*)(Bload + (size_t)64 * ldb);

    {   // store tile 0 into buffer 0
        As2[0][2*lc  ][lm   ] = make_float2(fa0.x, fa0.y);
        As2[0][2*lc+1][lm   ] = make_float2(fa0.z, fa0.w);
        As2[0][2*lc  ][lm+64] = make_float2(fa1.x, fa1.y);
        As2[0][2*lc+1][lm+64] = make_float2(fa1.z, fa1.w);
        Bs2[0][2*lc  ][lm   ] = make_float2(fb0.x, fb0.y);
        Bs2[0][2*lc+1][lm   ] = make_float2(fb0.z, fb0.w);
        Bs2[0][2*lc  ][lm+64] = make_float2(fb1.x, fb1.y);
        Bs2[0][2*lc+1][lm+64] = make_float2(fb1.z, fb1.w);
    }
    __syncthreads();

    for (int kt = 0; kt < ntiles; kt++) {
        const int cur = kt & 1, nxt = cur ^ 1;
        if (kt + 1 < ntiles) {
            const float* Ap = Aload + (kt + 1) * BK;
            const float* Bp = Bload + (kt + 1) * BK;
            fa0 = *(const float4*)(Ap);
            fa1 = *(const float4*)(Ap + (size_t)64 * lda);
            fb0 = *(const float4*)(Bp);
            fb1 = *(const float4*)(Bp + (size_t)64 * ldb);
        }
        #pragma unroll
        for (int k2 = 0; k2 < BK2; k2++) {
            u64 a2[8], b2[8];
            #pragma unroll
            for (int i = 0; i < 8; i++)
                a2[i] = *(const u64*)&As2[cur][k2][tRow + 16*i];
            #pragma unroll
            for (int j = 0; j < 8; j++)
                b2[j] = *(const u64*)&Bs2[cur][k2][tCol + 16*j];
            #pragma unroll
            for (int i = 0; i < 8; i++)
                #pragma unroll
                for (int j = 0; j < 8; j++)
                    fma2(acc[i][j], a2[i], b2[j]);
        }
        if (kt + 1 < ntiles) {
            As2[nxt][2*lc  ][lm   ] = make_float2(fa0.x, fa0.y);
            As2[nxt][2*lc+1][lm   ] = make_float2(fa0.z, fa0.w);
            As2[nxt][2*lc  ][lm+64] = make_float2(fa1.x, fa1.y);
            As2[nxt][2*lc+1][lm+64] = make_float2(fa1.z, fa1.w);
            Bs2[nxt][2*lc  ][lm   ] = make_float2(fb0.x, fb0.y);
            Bs2[nxt][2*lc+1][lm   ] = make_float2(fb0.z, fb0.w);
            Bs2[nxt][2*lc  ][lm+64] = make_float2(fb1.x, fb1.y);
            Bs2[nxt][2*lc+1][lm+64] = make_float2(fb1.z, fb1.w);
        }
        __syncthreads();
    }

    #pragma unroll
    for (int i = 0; i < 8; i++) {
        const int m = blockM + tRow + 16*i;
        #pragma unroll
        for (int j = 0; j < 8; j++) {
            const int n = blockN + tCol + 16*j;
            float v = hsum2(acc[i][j]);
            if (MODE == 1) {
                v = (v + bias[n]) * scale;
                const int b = m & (BSZ-1);
                const int s = m >> 1;
                const int h = n >> 6;
                const int d = n & (HD-1);
                C[((size_t)(b*NH + h)*SEQ + s)*HD + d] = v;
            } else {
                C[(size_t)m*ldc + n] = v;
            }
        }
    }
}

// =====================================================================
// GEMM NN (ctx = attn @ V):  A[m,k] (k=SEQ), B[k,n] (n=HD). 256x64 tile.
// Epilogue scatters to g_ctx[(m*BSZ+b)*EMB + h*HD + n], bh = blockIdx.z.
// =====================================================================
__global__ __launch_bounds__(256, 1)
void gemm_nn_f2(const float* __restrict__ A, const float* __restrict__ B,
                float* __restrict__ C)
{
    constexpr int BM = 256, BK = 16, BK2 = 8, AMP = 258, BNP = 66;
    const int bh = blockIdx.z;
    A += (size_t)bh * SEQ * SEQ;
    B += (size_t)bh * SEQ * HD;

    __shared__ float2 As2[2][BK2][AMP];   // 33 KB
    __shared__ float2 Bs2[2][BK2][BNP];   // 8.4 KB

    const int tid  = threadIdx.x;
    const int tCol = tid & 7;             // n-group (8)
    const int tRow = tid >> 3;            // m-group (32)
    const int blockM = blockIdx.y * BM;

    // A loader: 1024 float4 -> 4 per thread
    const int lm = tid >> 2;              // 0..63 (+64,+128,+192)
    const int lc = tid & 3;
    const float* Aload = A + (size_t)(blockM + lm) * SEQ + lc * 4;

    // B loader: tids 0..127; k2 = tid>>4, n4 = tid&15 — loads rows 2k2, 2k2+1
    const bool bact = tid < 128;
    const int  bk2  = tid >> 4;
    const int  bn4  = tid & 15;
    const float* Bload = B + (size_t)(2*bk2) * HD + bn4 * 4;

    u64 acc[8][8];
    #pragma unroll
    for (int i = 0; i < 8; i++)
        #pragma unroll
        for (int j = 0; j < 8; j++) acc[i][j] = 0ull;

    const int ntiles = SEQ / BK;          // 128
    float4 fa[4], fb0, fb1;

    #pragma unroll
    for (int r = 0; r < 4; r++)
        fa[r] = *(const float4*)(Aload + (size_t)(64*r) * SEQ);
    if (bact) {
        fb0 = *(const float4*)(Bload);
        fb1 = *(const float4*)(Bload + HD);
    }
    {
        #pragma unroll
        for (int r = 0; r < 4; r++) {
            As2[0][2*lc  ][lm + 64*r] = make_float2(fa[r].x, fa[r].y);
            As2[0][2*lc+1][lm + 64*r] = make_float2(fa[r].z, fa[r].w);
        }
        if (bact) {
            Bs2[0][bk2][4*bn4+0] = make_float2(fb0.x, fb1.x);
            Bs2[0][bk2][4*bn4+1] = make_float2(fb0.y, fb1.y);
            Bs2[0][bk2][4*bn4+2] = make_float2(fb0.z, fb1.z);
            Bs2[0][bk2][4*bn4+3] = make_float2(fb0.w, fb1.w);
        }
    }
    __syncthreads();

    for (int kt = 0; kt < ntiles; kt++) {
        const int cur = kt & 1, nxt = cur ^ 1;
        if (kt + 1 < ntiles) {
            const float* Ap = Aload + (kt + 1) * BK;
            #pragma unroll
            for (int r = 0; r < 4; r++)
                fa[r] = *(const float4*)(Ap + (size_t)(64*r) * SEQ);
            if (bact) {
                const float* Bp = Bload + (size_t)(kt + 1) * BK * HD;
                fb0 = *(const float4*)(Bp);
                fb1 = *(const float4*)(Bp + HD);
            }
        }
        #pragma unroll
        for (int k2 = 0; k2 < BK2; k2++) {
            u64 a2[8], b2[8];
            #pragma unroll
            for (int i = 0; i < 8; i++)
                a2[i] = *(const u64*)&As2[cur][k2][tRow + 32*i];
            #pragma unroll
            for (int j = 0; j < 8; j++)
                b2[j] = *(const u64*)&Bs2[cur][k2][tCol + 8*j];
            #pragma unroll
            for (int i = 0; i < 8; i++)
                #pragma unroll
                for (int j = 0; j < 8; j++)
                    fma2(acc[i][j], a2[i], b2[j]);
        }
        if (kt + 1 < ntiles) {
            #pragma unroll
            for (int r = 0; r < 4; r++) {
                As2[nxt][2*lc  ][lm + 64*r] = make_float2(fa[r].x, fa[r].y);
                As2[nxt][2*lc+1][lm + 64*r] = make_float2(fa[r].z, fa[r].w);
            }
            if (bact) {
                Bs2[nxt][bk2][4*bn4+0] = make_float2(fb0.x, fb1.x);
                Bs2[nxt][bk2][4*bn4+1] = make_float2(fb0.y, fb1.y);
                Bs2[nxt][bk2][4*bn4+2] = make_float2(fb0.z, fb1.z);
                Bs2[nxt][bk2][4*bn4+3] = make_float2(fb0.w, fb1.w);
            }
        }
        __syncthreads();
    }

    const int b = bh >> 4;
    const int h = bh & 15;
    #pragma unroll
    for (int i = 0; i < 8; i++) {
        const int m = blockM + tRow + 32*i;
        #pragma unroll
        for (int j = 0; j < 8; j++) {
            const int n = tCol + 8*j;
            C[(size_t)(m*BSZ + b)*EMB + h*HD + n] = hsum2(acc[i][j]);
        }
    }
}

// ---------------- softmax + head-average fusion ----------------
__device__ __forceinline__ float warpMax(float v) {
    #pragma unroll
    for (int o = 16; o; o >>= 1) v = fmaxf(v, __shfl_xor_sync(0xffffffffu, v, o));
    return v;
}
__device__ __forceinline__ float warpSum(float v) {
    #pragma unroll
    for (int o = 16; o; o >>= 1) v += __shfl_xor_sync(0xffffffffu, v, o);
    return v;
}

// one block per (b,q); loops over 16 heads; softmax in place + running avg
__global__ void softmax_avg_kernel(float* __restrict__ attn, float* __restrict__ avg)
{
    __shared__ float red[8];
    const int bq = blockIdx.x;
    const int b = bq >> 11;          // SEQ = 2048
    const int q = bq & 2047;
    const int tid = threadIdx.x, lane = tid & 31, wid = tid >> 5;

    float4 a0 = make_float4(0.f,0.f,0.f,0.f);
    float4 a1 = make_float4(0.f,0.f,0.f,0.f);

    for (int h = 0; h < NH; h++) {
        float4* p4 = (float4*)(attn + ((size_t)(b*NH + h)*SEQ + q)*SEQ);
        float4 v0 = p4[tid];
        float4 v1 = p4[tid + 256];

        float m = fmaxf(fmaxf(fmaxf(v0.x, v0.y), fmaxf(v0.z, v0.w)),
                        fmaxf(fmaxf(v1.x, v1.y), fmaxf(v1.z, v1.w)));
        m = warpMax(m);
        if (lane == 0) red[wid] = m;
        __syncthreads();
        if (wid == 0) {
            float t = (lane < 8) ? red[lane] : -FLT_MAX;
            t = warpMax(t);
            if (lane == 0) red[0] = t;
        }
        __syncthreads();
        const float rowMax = red[0];
        __syncthreads();

        v0.x = __expf(v0.x - rowMax); v0.y = __expf(v0.y - rowMax);
        v0.z = __expf(v0.z - rowMax); v0.w = __expf(v0.w - rowMax);
        v1.x = __expf(v1.x - rowMax); v1.y = __expf(v1.y - rowMax);
        v1.z = __expf(v1.z - rowMax); v1.w = __expf(v1.w - rowMax);
        float s = v0.x + v0.y + v0.z + v0.w + v1.x + v1.y + v1.z + v1.w;
        s = warpSum(s);
        if (lane == 0) red[wid] = s;
        __syncthreads();
        if (wid == 0) {
            float t = (lane < 8) ? red[lane] : 0.f;
            t = warpSum(t);
            if (lane == 0) red[0] = t;
        }
        __syncthreads();
        const float inv = 1.f / red[0];
        __syncthreads();

        v0.x *= inv; v0.y *= inv; v0.z *= inv; v0.w *= inv;
        v1.x *= inv; v1.y *= inv; v1.z *= inv; v1.w *= inv;
        p4[tid]       = v0;
        p4[tid + 256] = v1;
        a0.x += v0.x; a0.y += v0.y; a0.z += v0.z; a0.w += v0.w;
        a1.x += v1.x; a1.y += v1.y; a1.z += v1.z; a1.w += v1.w;
    }

    const float invH = 1.f / NH;
    a0.x *= invH; a0.y *= invH; a0.z *= invH; a0.w *= invH;
    a1.x *= invH; a1.y *= invH; a1.z *= invH; a1.w *= invH;
    float4* o4 = (float4*)(avg + ((size_t)b*SEQ + q)*SEQ);
    o4[tid]       = a0;
    o4[tid + 256] = a1;
}

// ---------------- launch ----------------
extern "C" void kernel_launch(void* const* d_in, const int* in_sizes, int n_in,
                              void* d_out, int out_size)
{
    const float* query   = (const float*)d_in[0];
    const float* key     = (const float*)d_in[1];
    const float* value   = (const float*)d_in[2];
    const float* q_w     = (const float*)d_in[3];
    const float* q_b     = (const float*)d_in[4];
    const float* k_w     = (const float*)d_in[5];
    const float* k_b     = (const float*)d_in[6];
    const float* v_w     = (const float*)d_in[7];
    const float* v_b     = (const float*)d_in[8];
    const float* ow_mean = (const float*)d_in[9];
    const float* ow_lg   = (const float*)d_in[10];
    const float* eps     = (const float*)d_in[11];

    float* out_main = (float*)d_out;
    float* out_avg  = out_main + (size_t)MROWS * EMB;

    float *q_p, *k_p, *v_p, *attn_p, *ctx_p, *ow_p;
    cudaGetSymbolAddress((void**)&q_p,    g_q);
    cudaGetSymbolAddress((void**)&k_p,    g_k);
    cudaGetSymbolAddress((void**)&v_p,    g_v);
    cudaGetSymbolAddress((void**)&attn_p, g_attn);
    cudaGetSymbolAddress((void**)&ctx_p,  g_ctx);
    cudaGetSymbolAddress((void**)&ow_p,   g_ow);

    // 1. sampled output weight
    ow_kernel<<<(EMB*EMB + 255)/256, 256>>>(ow_mean, ow_lg, eps);

    // 2. Q/K/V projections (scatter to [bh][s][d], bias + scale fused)
    const dim3 gProj(EMB/128, MROWS/128, 1);
    gemm_nt_f2<1><<<gProj, 256>>>(query, q_w, q_p, EMB, EMB, EMB, 0,
                                  0, 0, 0, q_b, 0.125f);
    gemm_nt_f2<1><<<gProj, 256>>>(key,   k_w, k_p, EMB, EMB, EMB, 0,
                                  0, 0, 0, k_b, 1.0f);
    gemm_nt_f2<1><<<gProj, 256>>>(value, v_w, v_p, EMB, EMB, EMB, 0,
                                  0, 0, 0, v_b, 1.0f);

    // 3. scores = Q K^T  (batched over bh)
    const dim3 gScore(SEQ/128, SEQ/128, BH);
    gemm_nt_f2<0><<<gScore, 256>>>(q_p, k_p, attn_p, HD, HD, HD, SEQ,
                                   (size_t)SEQ*HD, (size_t)SEQ*HD,
                                   (size_t)SEQ*SEQ, nullptr, 1.0f);

    // 4. softmax (in place) + head-average fused
    softmax_avg_kernel<<<BSZ*SEQ, 256>>>(attn_p, out_avg);

    // 5. ctx = attn @ V  (batched, scattered to [m][e])
    const dim3 gCtx(1, SEQ/256, BH);
    gemm_nn_f2<<<gCtx, 256>>>(attn_p, v_p, ctx_p);

    // 6. out = ctx @ o_w^T
    const dim3 gOut(EMB/128, MROWS/128, 1);
    gemm_nt_f2<0><<<gOut, 256>>>(ctx_p, ow_p, out_main, EMB, EMB, EMB, EMB,
                                 0, 0, 0, nullptr, 1.0f);
}

// round 4
// speedup vs baseline: 2.7291x; 2.1062x over previous
#include <cuda_runtime.h>
#include <cuda_bf16.h>
#include <math.h>
#include <float.h>

// ---------------- problem constants ----------------
#define SEQ  2048
#define BSZ  2
#define EMB  1024
#define NH   16
#define HD   64
#define BH   (BSZ*NH)          // 32
#define MROWS (SEQ*BSZ)        // 4096

// ---------------- scratch (static device arrays) ----------------
__device__ __align__(1024) __nv_bfloat16 s_xq_hi[(size_t)MROWS*EMB];
__device__ __align__(1024) __nv_bfloat16 s_xq_lo[(size_t)MROWS*EMB];
__device__ __align__(1024) __nv_bfloat16 s_xk_hi[(size_t)MROWS*EMB];
__device__ __align__(1024) __nv_bfloat16 s_xk_lo[(size_t)MROWS*EMB];
__device__ __align__(1024) __nv_bfloat16 s_xv_hi[(size_t)MROWS*EMB];
__device__ __align__(1024) __nv_bfloat16 s_xv_lo[(size_t)MROWS*EMB];
__device__ __align__(1024) __nv_bfloat16 s_wq_hi[(size_t)EMB*EMB];
__device__ __align__(1024) __nv_bfloat16 s_wq_lo[(size_t)EMB*EMB];
__device__ __align__(1024) __nv_bfloat16 s_wk_hi[(size_t)EMB*EMB];
__device__ __align__(1024) __nv_bfloat16 s_wk_lo[(size_t)EMB*EMB];
__device__ __align__(1024) __nv_bfloat16 s_wv_hi[(size_t)EMB*EMB];
__device__ __align__(1024) __nv_bfloat16 s_wv_lo[(size_t)EMB*EMB];
__device__ __align__(1024) __nv_bfloat16 s_ow_hi[(size_t)EMB*EMB];
__device__ __align__(1024) __nv_bfloat16 s_ow_lo[(size_t)EMB*EMB];
__device__ __align__(1024) __nv_bfloat16 s_q_hi[(size_t)BH*SEQ*HD];
__device__ __align__(1024) __nv_bfloat16 s_q_lo[(size_t)BH*SEQ*HD];
__device__ __align__(1024) __nv_bfloat16 s_k_hi[(size_t)BH*SEQ*HD];
__device__ __align__(1024) __nv_bfloat16 s_k_lo[(size_t)BH*SEQ*HD];
__device__ __align__(1024) __nv_bfloat16 s_v_hi[(size_t)BH*HD*SEQ];  // [bh][d][s]
__device__ __align__(1024) __nv_bfloat16 s_v_lo[(size_t)BH*HD*SEQ];
__device__ __align__(1024) float         g_attn[(size_t)BH*SEQ*SEQ]; // 512 MB
__device__ __align__(1024) __nv_bfloat16 s_p_hi[(size_t)BH*SEQ*SEQ]; // 256 MB
__device__ __align__(1024) __nv_bfloat16 s_p_lo[(size_t)BH*SEQ*SEQ]; // 256 MB
__device__ __align__(1024) __nv_bfloat16 s_c_hi[(size_t)MROWS*EMB];
__device__ __align__(1024) __nv_bfloat16 s_c_lo[(size_t)MROWS*EMB];

// ---------------- PTX helpers ----------------
__device__ __forceinline__ unsigned smem_u32(const void* p) {
    unsigned a;
    asm("{ .reg .u64 t; cvta.to.shared.u64 t, %1; cvt.u32.u64 %0, t; }"
        : "=r"(a) : "l"(p));
    return a;
}
__device__ __forceinline__ void cpasync16(unsigned dst, const void* src) {
    asm volatile("cp.async.cg.shared.global [%0], [%1], 16;" :: "r"(dst), "l"(src));
}
#define CP_COMMIT() asm volatile("cp.async.commit_group;" ::: "memory")
#define CP_WAIT0()  asm volatile("cp.async.wait_group 0;" ::: "memory")

__device__ __forceinline__ void ldsm4(unsigned r[4], unsigned addr) {
    asm volatile("ldmatrix.sync.aligned.m8n8.x4.shared.b16 {%0,%1,%2,%3}, [%4];"
        : "=r"(r[0]), "=r"(r[1]), "=r"(r[2]), "=r"(r[3]) : "r"(addr));
}
__device__ __forceinline__ void mma_bf16(float* d, const unsigned a[4],
                                         unsigned b0, unsigned b1) {
    asm volatile("mma.sync.aligned.m16n8k16.row.col.f32.bf16.bf16.f32 "
        "{%0,%1,%2,%3}, {%4,%5,%6,%7}, {%8,%9}, {%0,%1,%2,%3};"
        : "+f"(d[0]), "+f"(d[1]), "+f"(d[2]), "+f"(d[3])
        : "r"(a[0]), "r"(a[1]), "r"(a[2]), "r"(a[3]), "r"(b0), "r"(b1));
}
__device__ __forceinline__ void bsplit(float v, __nv_bfloat16& h, __nv_bfloat16& l) {
    h = __float2bfloat16(v);
    l = __float2bfloat16(v - __bfloat162float(h));
}
// swizzled byte offset within a tile of 64B rows (4 x 16B chunks per row)
__device__ __forceinline__ unsigned swz(int row, int chunk) {
    return (unsigned)(row * 64 + ((chunk ^ ((row >> 1) & 3)) << 4));
}

// ---------------- conversion kernels ----------------
__global__ void split_kernel(const float* __restrict__ x,
                             __nv_bfloat16* __restrict__ hi,
                             __nv_bfloat16* __restrict__ lo, int n4)
{
    int i = blockIdx.x * blockDim.x + threadIdx.x;
    if (i >= n4) return;
    float4 v = ((const float4*)x)[i];
    __nv_bfloat162 h0, h1, l0, l1;
    bsplit(v.x, h0.x, l0.x); bsplit(v.y, h0.y, l0.y);
    bsplit(v.z, h1.x, l1.x); bsplit(v.w, h1.y, l1.y);
    ((__nv_bfloat162*)hi)[2*i]   = h0;
    ((__nv_bfloat162*)hi)[2*i+1] = h1;
    ((__nv_bfloat162*)lo)[2*i]   = l0;
    ((__nv_bfloat162*)lo)[2*i+1] = l1;
}

__global__ void ow_split_kernel(const float* __restrict__ mean,
                                const float* __restrict__ lgstd,
                                const float* __restrict__ eps, int n4)
{
    int i = blockIdx.x * blockDim.x + threadIdx.x;
    if (i >= n4) return;
    float4 m = ((const float4*)mean)[i];
    float4 g = ((const float4*)lgstd)[i];
    float4 e = ((const float4*)eps)[i];
    float4 w = make_float4(m.x + e.x * expf(g.x), m.y + e.y * expf(g.y),
                           m.z + e.z * expf(g.z), m.w + e.w * expf(g.w));
    __nv_bfloat162 h0, h1, l0, l1;
    bsplit(w.x, h0.x, l0.x); bsplit(w.y, h0.y, l0.y);
    bsplit(w.z, h1.x, l1.x); bsplit(w.w, h1.y, l1.y);
    ((__nv_bfloat162*)s_ow_hi)[2*i]   = h0;
    ((__nv_bfloat162*)s_ow_hi)[2*i+1] = h1;
    ((__nv_bfloat162*)s_ow_lo)[2*i]   = l0;
    ((__nv_bfloat162*)s_ow_lo)[2*i+1] = l1;
}

// =====================================================================
// bf16x3 HMMA GEMM NT: D[m,n] = sum_k A[m,k]*B[n,k]  (fp32 accumulate)
// CTA 128 x BN, BK=32 bf16; 8 warps; cp.async double buffer; ldmatrix.
// 3 mma terms: Ahi*Bhi + Ahi*Blo + Alo*Bhi.
// MODE 0: fp32 plain (Cf + z*sC + m*ldc + n)
// MODE 1: split + bias + scale -> q/k layout [bh][s][d]
// MODE 2: split + bias         -> v layout [bh][d][s]
// MODE 3: split                -> ctx layout [(q*BSZ+b)*EMB + h*HD + d]
// =====================================================================
template<int BN, int WROWS, int MODE>
__global__ __launch_bounds__(256, 1)
void gemm_mma(const __nv_bfloat16* __restrict__ Ahi, const __nv_bfloat16* __restrict__ Alo,
              const __nv_bfloat16* __restrict__ Bhi_, const __nv_bfloat16* __restrict__ Blo_,
              int lda, int ldb, int K,
              size_t sA, size_t sB, size_t sC,
              float* __restrict__ Cf, int ldc,
              __nv_bfloat16* __restrict__ Chi, __nv_bfloat16* __restrict__ Clo,
              const float* __restrict__ bias, float scale)
{
    constexpr int BM = 128, BK = 32;
    constexpr int WCOLS = 8 / WROWS;
    constexpr int WM = BM / (WROWS * 16);   // m16 frags per warp
    constexpr int WN = BN / (WCOLS * 8);    // n8 frags per warp
    constexpr int ABYTES = BM * 64;         // one matrix (hi or lo), 64B/row
    constexpr int BBYTES = BN * 64;
    constexpr int BUF = 2 * ABYTES + 2 * BBYTES;

    extern __shared__ char smem[];
    const unsigned sb = smem_u32(smem);

    const int tid = threadIdx.x;
    const int l   = tid & 31;
    const int w   = tid >> 5;
    const int warp_m = (w % WROWS) * (WM * 16);
    const int warp_n = (w / WROWS) * (WN * 8);

    const int z = blockIdx.z;
    Ahi  += (size_t)z * sA;  Alo  += (size_t)z * sA;
    Bhi_ += (size_t)z * sB;  Blo_ += (size_t)z * sB;
    const int blockM = blockIdx.y * BM;
    const int blockN = blockIdx.x * BN;

    float acc[WM][WN][4];
    #pragma unroll
    for (int i = 0; i < WM; i++)
        #pragma unroll
        for (int j = 0; j < WN; j++)
            #pragma unroll
            for (int r = 0; r < 4; r++) acc[i][j][r] = 0.f;

    const int NK = K / BK;
    const int aq = l >> 3, ar = l & 7;   // ldmatrix lane decomposition

    auto load_tile = [&](int kt) {
        const unsigned tb = sb + (kt & 1) * BUF;
        #pragma unroll
        for (int t = 0; t < 2; t++) {                  // A: 512 chunks
            int i = tid + t * 256;
            int row = i >> 2, c = i & 3;
            size_t g = (size_t)(blockM + row) * lda + (size_t)kt * BK + c * 8;
            unsigned d = tb + swz(row, c);
            cpasync16(d,          Ahi + g);
            cpasync16(d + ABYTES, Alo + g);
        }
        #pragma unroll
        for (int t = 0; t < BN / 64; t++) {            // B: BN*4 chunks
            int i = tid + t * 256;
            int row = i >> 2, c = i & 3;
            size_t g = (size_t)(blockN + row) * ldb + (size_t)kt * BK + c * 8;
            unsigned d = tb + 2 * ABYTES + swz(row, c);
            cpasync16(d,          Bhi_ + g);
            cpasync16(d + BBYTES, Blo_ + g);
        }
        CP_COMMIT();
    };

    load_tile(0);

    for (int kt = 0; kt < NK; kt++) {
        CP_WAIT0();
        __syncthreads();
        if (kt + 1 < NK) load_tile(kt + 1);
        const unsigned tb = sb + (kt & 1) * BUF;

        #pragma unroll
        for (int ks = 0; ks < 2; ks++) {               // two k16 steps
            unsigned ah[WM][4], al_[WM][4];
            #pragma unroll
            for (int mi = 0; mi < WM; mi++) {
                int row = warp_m + mi * 16 + ar + 8 * (aq & 1);
                int c   = ks * 2 + (aq >> 1);
                unsigned ad = tb + swz(row, c);
                ldsm4(ah[mi],  ad);
                ldsm4(al_[mi], ad + ABYTES);
            }
            unsigned bh2[WN/2][4], bl2[WN/2][4];
            #pragma unroll
            for (int np = 0; np < WN / 2; np++) {
                int row = warp_n + np * 16 + ar + 8 * (aq >> 1);
                int c   = ks * 2 + (aq & 1);
                unsigned bd = tb + 2 * ABYTES + swz(row, c);
                ldsm4(bh2[np], bd);
                ldsm4(bl2[np], bd + BBYTES);
            }
            #pragma unroll
            for (int mi = 0; mi < WM; mi++)
                #pragma unroll
                for (int nj = 0; nj < WN; nj++) {
                    const unsigned* bh = &bh2[nj >> 1][(nj & 1) * 2];
                    const unsigned* bl = &bl2[nj >> 1][(nj & 1) * 2];
                    mma_bf16(acc[mi][nj], ah[mi],  bh[0], bh[1]);
                    mma_bf16(acc[mi][nj], ah[mi],  bl[0], bl[1]);
                    mma_bf16(acc[mi][nj], al_[mi], bh[0], bh[1]);
                }
        }
    }

    // ---------------- epilogue ----------------
    #pragma unroll
    for (int mi = 0; mi < WM; mi++) {
        #pragma unroll
        for (int nj = 0; nj < WN; nj++) {
            float* a = acc[mi][nj];
            const int m0 = blockM + warp_m + mi * 16 + (l >> 2);
            const int n0 = blockN + warp_n + nj * 8 + (l & 3) * 2;
            if (MODE == 0) {
                float* base = Cf + (size_t)z * sC;
                *(float2*)(base + (size_t)m0 * ldc + n0)       = make_float2(a[0], a[1]);
                *(float2*)(base + (size_t)(m0 + 8) * ldc + n0) = make_float2(a[2], a[3]);
            } else if (MODE == 1) {
                const float b0 = bias[n0], b1 = bias[n0 + 1];
                const int h = n0 >> 6, d = n0 & 63;
                #pragma unroll
                for (int r = 0; r < 2; r++) {
                    const int m = m0 + 8 * r;
                    const int b = m & 1, s = m >> 1;
                    float v0 = (a[2*r]   + b0) * scale;
                    float v1 = (a[2*r+1] + b1) * scale;
                    size_t o = ((size_t)(b * NH + h) * SEQ + s) * HD + d;
                    __nv_bfloat162 hh, ll;
                    bsplit(v0, hh.x, ll.x); bsplit(v1, hh.y, ll.y);
                    *(__nv_bfloat162*)(Chi + o) = hh;
                    *(__nv_bfloat162*)(Clo + o) = ll;
                }
            } else if (MODE == 2) {
                const float b0 = bias[n0], b1 = bias[n0 + 1];
                const int h = n0 >> 6, d = n0 & 63;
                #pragma unroll
                for (int r = 0; r < 2; r++) {
                    const int m = m0 + 8 * r;
                    const int b = m & 1, s = m >> 1;
                    float v0 = a[2*r]   + b0;
                    float v1 = a[2*r+1] + b1;
                    size_t o0 = ((size_t)(b * NH + h) * HD + d)     * SEQ + s;
                    size_t o1 = ((size_t)(b * NH + h) * HD + d + 1) * SEQ + s;
                    __nv_bfloat16 hh, ll;
                    bsplit(v0, hh, ll); Chi[o0] = hh; Clo[o0] = ll;
                    bsplit(v1, hh, ll); Chi[o1] = hh; Clo[o1] = ll;
                }
            } else {  // MODE 3: ctx
                const int b = z >> 4, h = z & 15;
                #pragma unroll
                for (int r = 0; r < 2; r++) {
                    const int m = m0 + 8 * r;
                    size_t o = ((size_t)m * BSZ + b) * EMB + h * HD + n0;
                    __nv_bfloat162 hh, ll;
                    bsplit(a[2*r],   hh.x, ll.x);
                    bsplit(a[2*r+1], hh.y, ll.y);
                    *(__nv_bfloat162*)(Chi + o) = hh;
                    *(__nv_bfloat162*)(Clo + o) = ll;
                }
            }
        }
    }
}

// ---------------- softmax + head-average + bf16 split ----------------
__device__ __forceinline__ float warpMax(float v) {
    #pragma unroll
    for (int o = 16; o; o >>= 1) v = fmaxf(v, __shfl_xor_sync(0xffffffffu, v, o));
    return v;
}
__device__ __forceinline__ float warpSum(float v) {
    #pragma unroll
    for (int o = 16; o; o >>= 1) v += __shfl_xor_sync(0xffffffffu, v, o);
    return v;
}

__global__ void softmax_avg_kernel(const float* __restrict__ attn,
                                   float* __restrict__ avg)
{
    __shared__ float red[8];
    const int bq = blockIdx.x;
    const int b = bq >> 11;
    const int q = bq & 2047;
    const int tid = threadIdx.x, lane = tid & 31, wid = tid >> 5;

    float4 a0 = make_float4(0.f, 0.f, 0.f, 0.f);
    float4 a1 = make_float4(0.f, 0.f, 0.f, 0.f);

    for (int h = 0; h < NH; h++) {
        const size_t rowoff = ((size_t)(b * NH + h) * SEQ + q) * SEQ;
        const float4* p4 = (const float4*)(attn + rowoff);
        float4 v0 = p4[tid];
        float4 v1 = p4[tid + 256];

        float mx = fmaxf(fmaxf(fmaxf(v0.x, v0.y), fmaxf(v0.z, v0.w)),
                         fmaxf(fmaxf(v1.x, v1.y), fmaxf(v1.z, v1.w)));
        mx = warpMax(mx);
        if (lane == 0) red[wid] = mx;
        __syncthreads();
        if (wid == 0) {
            float t = (lane < 8) ? red[lane] : -FLT_MAX;
            t = warpMax(t);
            if (lane == 0) red[0] = t;
        }
        __syncthreads();
        const float rowMax = red[0];
        __syncthreads();

        v0.x = __expf(v0.x - rowMax); v0.y = __expf(v0.y - rowMax);
        v0.z = __expf(v0.z - rowMax); v0.w = __expf(v0.w - rowMax);
        v1.x = __expf(v1.x - rowMax); v1.y = __expf(v1.y - rowMax);
        v1.z = __expf(v1.z - rowMax); v1.w = __expf(v1.w - rowMax);
        float sv = v0.x + v0.y + v0.z + v0.w + v1.x + v1.y + v1.z + v1.w;
        sv = warpSum(sv);
        if (lane == 0) red[wid] = sv;
        __syncthreads();
        if (wid == 0) {
            float t = (lane < 8) ? red[lane] : 0.f;
            t = warpSum(t);
            if (lane == 0) red[0] = t;
        }
        __syncthreads();
        const float inv = 1.f / red[0];
        __syncthreads();

        v0.x *= inv; v0.y *= inv; v0.z *= inv; v0.w *= inv;
        v1.x *= inv; v1.y *= inv; v1.z *= inv; v1.w *= inv;

        __nv_bfloat162* ph2 = (__nv_bfloat162*)(s_p_hi + rowoff);
        __nv_bfloat162* pl2 = (__nv_bfloat162*)(s_p_lo + rowoff);
        __nv_bfloat162 h0, h1, l0, l1;
        bsplit(v0.x, h0.x, l0.x); bsplit(v0.y, h0.y, l0.y);
        bsplit(v0.z, h1.x, l1.x); bsplit(v0.w, h1.y, l1.y);
        ph2[2*tid] = h0; ph2[2*tid+1] = h1;
        pl2[2*tid] = l0; pl2[2*tid+1] = l1;
        bsplit(v1.x, h0.x, l0.x); bsplit(v1.y, h0.y, l0.y);
        bsplit(v1.z, h1.x, l1.x); bsplit(v1.w, h1.y, l1.y);
        ph2[2*(tid+256)] = h0; ph2[2*(tid+256)+1] = h1;
        pl2[2*(tid+256)] = l0; pl2[2*(tid+256)+1] = l1;

        a0.x += v0.x; a0.y += v0.y; a0.z += v0.z; a0.w += v0.w;
        a1.x += v1.x; a1.y += v1.y; a1.z += v1.z; a1.w += v1.w;
    }

    const float invH = 1.f / NH;
    a0.x *= invH; a0.y *= invH; a0.z *= invH; a0.w *= invH;
    a1.x *= invH; a1.y *= invH; a1.z *= invH; a1.w *= invH;
    float4* o4 = (float4*)(avg + ((size_t)b * SEQ + q) * SEQ);
    o4[tid]       = a0;
    o4[tid + 256] = a1;
}

// ---------------- launch ----------------
extern "C" void kernel_launch(void* const* d_in, const int* in_sizes, int n_in,
                              void* d_out, int out_size)
{
    const float* query   = (const float*)d_in[0];
    const float* key     = (const float*)d_in[1];
    const float* value   = (const float*)d_in[2];
    const float* q_w     = (const float*)d_in[3];
    const float* q_b     = (const float*)d_in[4];
    const float* k_w     = (const float*)d_in[5];
    const float* k_b     = (const float*)d_in[6];
    const float* v_w     = (const float*)d_in[7];
    const float* v_b     = (const float*)d_in[8];
    const float* ow_mean = (const float*)d_in[9];
    const float* ow_lg   = (const float*)d_in[10];
    const float* eps     = (const float*)d_in[11];

    float* out_main = (float*)d_out;
    float* out_avg  = out_main + (size_t)MROWS * EMB;

    __nv_bfloat16 *xqh,*xql,*xkh,*xkl,*xvh,*xvl,*wqh,*wql,*wkh,*wkl,*wvh,*wvl;
    __nv_bfloat16 *owh,*owl,*qh,*ql,*kh,*kl,*vh,*vl,*pph,*ppl,*ch,*cl;
    float* attn_p;
    cudaGetSymbolAddress((void**)&xqh, s_xq_hi); cudaGetSymbolAddress((void**)&xql, s_xq_lo);
    cudaGetSymbolAddress((void**)&xkh, s_xk_hi); cudaGetSymbolAddress((void**)&xkl, s_xk_lo);
    cudaGetSymbolAddress((void**)&xvh, s_xv_hi); cudaGetSymbolAddress((void**)&xvl, s_xv_lo);
    cudaGetSymbolAddress((void**)&wqh, s_wq_hi); cudaGetSymbolAddress((void**)&wql, s_wq_lo);
    cudaGetSymbolAddress((void**)&wkh, s_wk_hi); cudaGetSymbolAddress((void**)&wkl, s_wk_lo);
    cudaGetSymbolAddress((void**)&wvh, s_wv_hi); cudaGetSymbolAddress((void**)&wvl, s_wv_lo);
    cudaGetSymbolAddress((void**)&owh, s_ow_hi); cudaGetSymbolAddress((void**)&owl, s_ow_lo);
    cudaGetSymbolAddress((void**)&qh,  s_q_hi);  cudaGetSymbolAddress((void**)&ql,  s_q_lo);
    cudaGetSymbolAddress((void**)&kh,  s_k_hi);  cudaGetSymbolAddress((void**)&kl,  s_k_lo);
    cudaGetSymbolAddress((void**)&vh,  s_v_hi);  cudaGetSymbolAddress((void**)&vl,  s_v_lo);
    cudaGetSymbolAddress((void**)&pph, s_p_hi);  cudaGetSymbolAddress((void**)&ppl, s_p_lo);
    cudaGetSymbolAddress((void**)&ch,  s_c_hi);  cudaGetSymbolAddress((void**)&cl,  s_c_lo);
    cudaGetSymbolAddress((void**)&attn_p, g_attn);

    // dynamic smem: BN=128 -> 64 KB; BN=64 -> 48 KB
    const int SMEM128 = 2 * (2 * 128 * 64 + 2 * 128 * 64);
    const int SMEM64  = 2 * (2 * 128 * 64 + 2 * 64 * 64);
    cudaFuncSetAttribute(gemm_mma<128,2,0>, cudaFuncAttributeMaxDynamicSharedMemorySize, SMEM128);
    cudaFuncSetAttribute(gemm_mma<128,2,1>, cudaFuncAttributeMaxDynamicSharedMemorySize, SMEM128);
    cudaFuncSetAttribute(gemm_mma<128,2,2>, cudaFuncAttributeMaxDynamicSharedMemorySize, SMEM128);
    cudaFuncSetAttribute(gemm_mma<64,4,3>,  cudaFuncAttributeMaxDynamicSharedMemorySize, SMEM64);

    // 1. split inputs + weights, sample output weight
    const int nx4 = MROWS * EMB / 4, nw4 = EMB * EMB / 4;
    split_kernel<<<(nx4 + 255)/256, 256>>>(query, xqh, xql, nx4);
    split_kernel<<<(nx4 + 255)/256, 256>>>(key,   xkh, xkl, nx4);
    split_kernel<<<(nx4 + 255)/256, 256>>>(value, xvh, xvl, nx4);
    split_kernel<<<(nw4 + 255)/256, 256>>>(q_w, wqh, wql, nw4);
    split_kernel<<<(nw4 + 255)/256, 256>>>(k_w, wkh, wkl, nw4);
    split_kernel<<<(nw4 + 255)/256, 256>>>(v_w, wvh, wvl, nw4);
    ow_split_kernel<<<(nw4 + 255)/256, 256>>>(ow_mean, ow_lg, eps, nw4);

    // 2. Q/K/V projections
    const dim3 gProj(EMB/128, MROWS/128, 1);
    gemm_mma<128,2,1><<<gProj, 256, SMEM128>>>(xqh, xql, wqh, wql, EMB, EMB, EMB,
                                               0, 0, 0, nullptr, 0, qh, ql, q_b, 0.125f);
    gemm_mma<128,2,1><<<gProj, 256, SMEM128>>>(xkh, xkl, wkh, wkl, EMB, EMB, EMB,
                                               0, 0, 0, nullptr, 0, kh, kl, k_b, 1.0f);
    gemm_mma<128,2,2><<<gProj, 256, SMEM128>>>(xvh, xvl, wvh, wvl, EMB, EMB, EMB,
                                               0, 0, 0, nullptr, 0, vh, vl, v_b, 1.0f);

    // 3. scores = Q K^T (batched over bh), fp32 out
    const dim3 gScore(SEQ/128, SEQ/128, BH);
    gemm_mma<128,2,0><<<gScore, 256, SMEM128>>>(qh, ql, kh, kl, HD, HD, HD,
                                                (size_t)SEQ*HD, (size_t)SEQ*HD,
                                                (size_t)SEQ*SEQ, attn_p, SEQ,
                                                nullptr, nullptr, nullptr, 1.0f);

    // 4. softmax + avg + bf16 split of probs
    softmax_avg_kernel<<<BSZ*SEQ, 256>>>(attn_p, out_avg);

    // 5. ctx = P @ V  (batched; V stored [bh][d][s] -> NT form)
    const dim3 gCtx(1, SEQ/128, BH);
    gemm_mma<64,4,3><<<gCtx, 256, SMEM64>>>(pph, ppl, vh, vl, SEQ, SEQ, SEQ,
                                            (size_t)SEQ*SEQ, (size_t)HD*SEQ, 0,
                                            nullptr, 0, ch, cl, nullptr, 1.0f);

    // 6. out = ctx @ o_w^T  (fp32 out)
    const dim3 gOut(EMB/128, MROWS/128, 1);
    gemm_mma<128,2,0><<<gOut, 256, SMEM128>>>(ch, cl, owh, owl, EMB, EMB, EMB,
                                              0, 0, 0, out_main, EMB,
                                              nullptr, nullptr, nullptr, 1.0f);
}

// round 6
// speedup vs baseline: 2.9583x; 1.0840x over previous
#include <cuda_runtime.h>
#include <cuda_bf16.h>
#include <math.h>
#include <float.h>

// ---------------- problem constants ----------------
#define SEQ  2048
#define BSZ  2
#define EMB  1024
#define NH   16
#define HD   64
#define BH   (BSZ*NH)          // 32
#define MROWS (SEQ*BSZ)        // 4096

// ---------------- scratch (static device arrays) ----------------
__device__ __align__(1024) __nv_bfloat16 s_xq_hi[(size_t)MROWS*EMB];
__device__ __align__(1024) __nv_bfloat16 s_xq_lo[(size_t)MROWS*EMB];
__device__ __align__(1024) __nv_bfloat16 s_xk_hi[(size_t)MROWS*EMB];
__device__ __align__(1024) __nv_bfloat16 s_xk_lo[(size_t)MROWS*EMB];
__device__ __align__(1024) __nv_bfloat16 s_xv_hi[(size_t)MROWS*EMB];
__device__ __align__(1024) __nv_bfloat16 s_xv_lo[(size_t)MROWS*EMB];
__device__ __align__(1024) __nv_bfloat16 s_wq_hi[(size_t)EMB*EMB];
__device__ __align__(1024) __nv_bfloat16 s_wq_lo[(size_t)EMB*EMB];
__device__ __align__(1024) __nv_bfloat16 s_wk_hi[(size_t)EMB*EMB];
__device__ __align__(1024) __nv_bfloat16 s_wk_lo[(size_t)EMB*EMB];
__device__ __align__(1024) __nv_bfloat16 s_wv_hi[(size_t)EMB*EMB];
__device__ __align__(1024) __nv_bfloat16 s_wv_lo[(size_t)EMB*EMB];
__device__ __align__(1024) __nv_bfloat16 s_ow_hi[(size_t)EMB*EMB];
__device__ __align__(1024) __nv_bfloat16 s_ow_lo[(size_t)EMB*EMB];
__device__ __align__(1024) __nv_bfloat16 s_q_hi[(size_t)BH*SEQ*HD];
__device__ __align__(1024) __nv_bfloat16 s_q_lo[(size_t)BH*SEQ*HD];
__device__ __align__(1024) __nv_bfloat16 s_k_hi[(size_t)BH*SEQ*HD];
__device__ __align__(1024) __nv_bfloat16 s_k_lo[(size_t)BH*SEQ*HD];
__device__ __align__(1024) __nv_bfloat16 s_v_hi[(size_t)BH*HD*SEQ];  // [bh][d][s]
__device__ __align__(1024) __nv_bfloat16 s_v_lo[(size_t)BH*HD*SEQ];
__device__ __align__(1024) float         g_attn[(size_t)BH*SEQ*SEQ]; // 512 MB
__device__ __align__(1024) __nv_bfloat16 s_p_hi[(size_t)BH*SEQ*SEQ]; // 256 MB
__device__ __align__(1024) __nv_bfloat16 s_p_lo[(size_t)BH*SEQ*SEQ]; // 256 MB
__device__ __align__(1024) __nv_bfloat16 s_c_hi[(size_t)MROWS*EMB];
__device__ __align__(1024) __nv_bfloat16 s_c_lo[(size_t)MROWS*EMB];

// ---------------- PTX helpers ----------------
__device__ __forceinline__ unsigned smem_u32(const void* p) {
    unsigned a;
    asm("{ .reg .u64 t; cvta.to.shared.u64 t, %1; cvt.u32.u64 %0, t; }"
        : "=r"(a) : "l"(p));
    return a;
}
__device__ __forceinline__ void cpasync16(unsigned dst, const void* src) {
    asm volatile("cp.async.cg.shared.global [%0], [%1], 16;" :: "r"(dst), "l"(src));
}
#define CP_COMMIT() asm volatile("cp.async.commit_group;" ::: "memory")
#define CP_WAIT0()  asm volatile("cp.async.wait_group 0;" ::: "memory")

__device__ __forceinline__ void ldsm4(unsigned r[4], unsigned addr) {
    asm volatile("ldmatrix.sync.aligned.m8n8.x4.shared.b16 {%0,%1,%2,%3}, [%4];"
        : "=r"(r[0]), "=r"(r[1]), "=r"(r[2]), "=r"(r[3]) : "r"(addr));
}
__device__ __forceinline__ void mma_bf16(float* d, const unsigned a[4],
                                         unsigned b0, unsigned b1) {
    asm volatile("mma.sync.aligned.m16n8k16.row.col.f32.bf16.bf16.f32 "
        "{%0,%1,%2,%3}, {%4,%5,%6,%7}, {%8,%9}, {%0,%1,%2,%3};"
        : "+f"(d[0]), "+f"(d[1]), "+f"(d[2]), "+f"(d[3])
        : "r"(a[0]), "r"(a[1]), "r"(a[2]), "r"(a[3]), "r"(b0), "r"(b1));
}
__device__ __forceinline__ void bsplit(float v, __nv_bfloat16& h, __nv_bfloat16& l) {
    h = __float2bfloat16(v);
    l = __float2bfloat16(v - __bfloat162float(h));
}
// swizzled byte offset within a tile of 64B rows (4 x 16B chunks per row)
__device__ __forceinline__ unsigned swz(int row, int chunk) {
    return (unsigned)(row * 64 + ((chunk ^ ((row >> 1) & 3)) << 4));
}

// ---------------- fused conversion kernels ----------------
struct Split6Args {
    const float*   src[6];
    __nv_bfloat16* hi[6];
    __nv_bfloat16* lo[6];
    int            n4[6];
};

__global__ void split6_kernel(Split6Args a)
{
    const int z = blockIdx.y;
    int i = blockIdx.x * blockDim.x + threadIdx.x;
    if (i >= a.n4[z]) return;
    float4 v = ((const float4*)a.src[z])[i];
    __nv_bfloat162 h0, h1, l0, l1;
    bsplit(v.x, h0.x, l0.x); bsplit(v.y, h0.y, l0.y);
    bsplit(v.z, h1.x, l1.x); bsplit(v.w, h1.y, l1.y);
    ((__nv_bfloat162*)a.hi[z])[2*i]   = h0;
    ((__nv_bfloat162*)a.hi[z])[2*i+1] = h1;
    ((__nv_bfloat162*)a.lo[z])[2*i]   = l0;
    ((__nv_bfloat162*)a.lo[z])[2*i+1] = l1;
}

__global__ void ow_split_kernel(const float* __restrict__ mean,
                                const float* __restrict__ lgstd,
                                const float* __restrict__ eps, int n4)
{
    int i = blockIdx.x * blockDim.x + threadIdx.x;
    if (i >= n4) return;
    float4 m = ((const float4*)mean)[i];
    float4 g = ((const float4*)lgstd)[i];
    float4 e = ((const float4*)eps)[i];
    float4 w = make_float4(m.x + e.x * expf(g.x), m.y + e.y * expf(g.y),
                           m.z + e.z * expf(g.z), m.w + e.w * expf(g.w));
    __nv_bfloat162 h0, h1, l0, l1;
    bsplit(w.x, h0.x, l0.x); bsplit(w.y, h0.y, l0.y);
    bsplit(w.z, h1.x, l1.x); bsplit(w.w, h1.y, l1.y);
    ((__nv_bfloat162*)s_ow_hi)[2*i]   = h0;
    ((__nv_bfloat162*)s_ow_hi)[2*i+1] = h1;
    ((__nv_bfloat162*)s_ow_lo)[2*i]   = l0;
    ((__nv_bfloat162*)s_ow_lo)[2*i+1] = l1;
}

// =====================================================================
// bf16x3 HMMA GEMM NT: D[m,n] = sum_k A[m,k]*B[n,k]  (fp32 accumulate)
// CTA 128 x 64, BK=32 bf16; 8 warps (4 x 2); 2 CTAs/SM target.
// cp.async double buffer; ldmatrix; 3 terms: Ahi*Bhi + Ahi*Blo + Alo*Bhi.
// MODE 0: fp32 plain (Cf + z*sC + m*ldc + n)
// MODE 1: split + bias + scale -> q/k layout [bh][s][d]
// MODE 2: split + bias         -> v layout [bh][d][s]
// MODE 3: split                -> ctx layout [(q*BSZ+b)*EMB + h*HD + d]
// =====================================================================
template<int MODE>
__global__ __launch_bounds__(256, 2)
void gemm_mma(const __nv_bfloat16* __restrict__ Ahi, const __nv_bfloat16* __restrict__ Alo,
              const __nv_bfloat16* __restrict__ Bhi_, const __nv_bfloat16* __restrict__ Blo_,
              int lda, int ldb, int K,
              size_t sA, size_t sB, size_t sC,
              float* __restrict__ Cf, int ldc,
              __nv_bfloat16* __restrict__ Chi, __nv_bfloat16* __restrict__ Clo,
              const float* __restrict__ bias, float scale)
{
    constexpr int BM = 128, BN = 64, BK = 32;
    constexpr int WM = 2;                   // m16 frags per warp (4 warp-rows)
    constexpr int WN = 4;                   // n8 frags per warp  (2 warp-cols)
    constexpr int ABYTES = BM * 64;         // one matrix (hi or lo), 64B/row
    constexpr int BBYTES = BN * 64;
    constexpr int BUF = 2 * ABYTES + 2 * BBYTES;  // 24 KB per stage

    extern __shared__ char smem[];
    const unsigned sb = smem_u32(smem);

    const int tid = threadIdx.x;
    const int l   = tid & 31;
    const int w   = tid >> 5;
    const int warp_m = (w & 3) * (WM * 16);   // 0,32,64,96
    const int warp_n = (w >> 2) * (WN * 8);   // 0,32

    const int z = blockIdx.z;
    Ahi  += (size_t)z * sA;  Alo  += (size_t)z * sA;
    Bhi_ += (size_t)z * sB;  Blo_ += (size_t)z * sB;
    const int blockM = blockIdx.y * BM;
    const int blockN = blockIdx.x * BN;

    float acc[WM][WN][4];
    #pragma unroll
    for (int i = 0; i < WM; i++)
        #pragma unroll
        for (int j = 0; j < WN; j++)
            #pragma unroll
            for (int r = 0; r < 4; r++) acc[i][j][r] = 0.f;

    const int NK = K / BK;
    const int aq = l >> 3, ar = l & 7;   // ldmatrix lane decomposition

    auto load_tile = [&](int kt) {
        const unsigned tb = sb + (kt & 1) * BUF;
        #pragma unroll
        for (int t = 0; t < 2; t++) {                  // A: 512 chunks
            int i = tid + t * 256;
            int row = i >> 2, c = i & 3;
            size_t g = (size_t)(blockM + row) * lda + (size_t)kt * BK + c * 8;
            unsigned d = tb + swz(row, c);
            cpasync16(d,          Ahi + g);
            cpasync16(d + ABYTES, Alo + g);
        }
        {                                              // B: 256 chunks
            int row = tid >> 2, c = tid & 3;
            size_t g = (size_t)(blockN + row) * ldb + (size_t)kt * BK + c * 8;
            unsigned d = tb + 2 * ABYTES + swz(row, c);
            cpasync16(d,          Bhi_ + g);
            cpasync16(d + BBYTES, Blo_ + g);
        }
        CP_COMMIT();
    };

    load_tile(0);

    for (int kt = 0; kt < NK; kt++) {
        CP_WAIT0();
        __syncthreads();
        if (kt + 1 < NK) load_tile(kt + 1);
        const unsigned tb = sb + (kt & 1) * BUF;

        #pragma unroll
        for (int ks = 0; ks < 2; ks++) {               // two k16 steps
            unsigned ah[WM][4], al_[WM][4];
            #pragma unroll
            for (int mi = 0; mi < WM; mi++) {
                int row = warp_m + mi * 16 + ar + 8 * (aq & 1);
                int c   = ks * 2 + (aq >> 1);
                unsigned ad = tb + swz(row, c);
                ldsm4(ah[mi],  ad);
                ldsm4(al_[mi], ad + ABYTES);
            }
            unsigned bh2[WN/2][4], bl2[WN/2][4];
            #pragma unroll
            for (int np = 0; np < WN / 2; np++) {
                int row = warp_n + np * 16 + ar + 8 * (aq >> 1);
                int c   = ks * 2 + (aq & 1);
                unsigned bd = tb + 2 * ABYTES + swz(row, c);
                ldsm4(bh2[np], bd);
                ldsm4(bl2[np], bd + BBYTES);
            }
            #pragma unroll
            for (int mi = 0; mi < WM; mi++)
                #pragma unroll
                for (int nj = 0; nj < WN; nj++) {
                    const unsigned* bh = &bh2[nj >> 1][(nj & 1) * 2];
                    const unsigned* bl = &bl2[nj >> 1][(nj & 1) * 2];
                    mma_bf16(acc[mi][nj], ah[mi],  bh[0], bh[1]);
                    mma_bf16(acc[mi][nj], ah[mi],  bl[0], bl[1]);
                    mma_bf16(acc[mi][nj], al_[mi], bh[0], bh[1]);
                }
        }
    }

    // ---------------- epilogue ----------------
    #pragma unroll
    for (int mi = 0; mi < WM; mi++) {
        #pragma unroll
        for (int nj = 0; nj < WN; nj++) {
            float* a = acc[mi][nj];
            const int m0 = blockM + warp_m + mi * 16 + (l >> 2);
            const int n0 = blockN + warp_n + nj * 8 + (l & 3) * 2;
            if (MODE == 0) {
                float* base = Cf + (size_t)z * sC;
                *(float2*)(base + (size_t)m0 * ldc + n0)       = make_float2(a[0], a[1]);
                *(float2*)(base + (size_t)(m0 + 8) * ldc + n0) = make_float2(a[2], a[3]);
            } else if (MODE == 1) {
                const float b0 = bias[n0], b1 = bias[n0 + 1];
                const int h = n0 >> 6, d = n0 & 63;
                #pragma unroll
                for (int r = 0; r < 2; r++) {
                    const int m = m0 + 8 * r;
                    const int b = m & 1, s = m >> 1;
                    float v0 = (a[2*r]   + b0) * scale;
                    float v1 = (a[2*r+1] + b1) * scale;
                    size_t o = ((size_t)(b * NH + h) * SEQ + s) * HD + d;
                    __nv_bfloat162 hh, ll;
                    bsplit(v0, hh.x, ll.x); bsplit(v1, hh.y, ll.y);
                    *(__nv_bfloat162*)(Chi + o) = hh;
                    *(__nv_bfloat162*)(Clo + o) = ll;
                }
            } else if (MODE == 2) {
                const float b0 = bias[n0], b1 = bias[n0 + 1];
                const int h = n0 >> 6, d = n0 & 63;
                #pragma unroll
                for (int r = 0; r < 2; r++) {
                    const int m = m0 + 8 * r;
                    const int b = m & 1, s = m >> 1;
                    float v0 = a[2*r]   + b0;
                    float v1 = a[2*r+1] + b1;
                    size_t o0 = ((size_t)(b * NH + h) * HD + d)     * SEQ + s;
                    size_t o1 = ((size_t)(b * NH + h) * HD + d + 1) * SEQ + s;
                    __nv_bfloat16 hh, ll;
                    bsplit(v0, hh, ll); Chi[o0] = hh; Clo[o0] = ll;
                    bsplit(v1, hh, ll); Chi[o1] = hh; Clo[o1] = ll;
                }
            } else {  // MODE 3: ctx
                const int b = z >> 4, h = z & 15;
                #pragma unroll
                for (int r = 0; r < 2; r++) {
                    const int m = m0 + 8 * r;
                    size_t o = ((size_t)m * BSZ + b) * EMB + h * HD + n0;
                    __nv_bfloat162 hh, ll;
                    bsplit(a[2*r],   hh.x, ll.x);
                    bsplit(a[2*r+1], hh.y, ll.y);
                    *(__nv_bfloat162*)(Chi + o) = hh;
                    *(__nv_bfloat162*)(Clo + o) = ll;
                }
            }
        }
    }
}

// ---------------- softmax + head-average + bf16 split ----------------
__device__ __forceinline__ float warpMax(float v) {
    #pragma unroll
    for (int o = 16; o; o >>= 1) v = fmaxf(v, __shfl_xor_sync(0xffffffffu, v, o));
    return v;
}
__device__ __forceinline__ float warpSum(float v) {
    #pragma unroll
    for (int o = 16; o; o >>= 1) v += __shfl_xor_sync(0xffffffffu, v, o);
    return v;
}

__global__ void softmax_avg_kernel(const float* __restrict__ attn,
                                   float* __restrict__ avg)
{
    __shared__ float red[8];
    const int bq = blockIdx.x;
    const int b = bq >> 11;          // SEQ = 2048
    const int q = bq & 2047;
    const int tid = threadIdx.x, lane = tid & 31, wid = tid >> 5;

    float4 a0 = make_float4(0.f, 0.f, 0.f, 0.f);
    float4 a1 = make_float4(0.f, 0.f, 0.f, 0.f);

    for (int h = 0; h < NH; h++) {
        const size_t rowoff = ((size_t)(b * NH + h) * SEQ + q) * SEQ;
        const float4* p4 = (const float4*)(attn + rowoff);
        float4 v0 = p4[tid];
        float4 v1 = p4[tid + 256];

        float mx = fmaxf(fmaxf(fmaxf(v0.x, v0.y), fmaxf(v0.z, v0.w)),
                         fmaxf(fmaxf(v1.x, v1.y), fmaxf(v1.z, v1.w)));
        mx = warpMax(mx);
        if (lane == 0) red[wid] = mx;
        __syncthreads();
        if (wid == 0) {
            float t = (lane < 8) ? red[lane] : -FLT_MAX;
            t = warpMax(t);
            if (lane == 0) red[0] = t;
        }
        __syncthreads();
        const float rowMax = red[0];
        __syncthreads();

        v0.x = __expf(v0.x - rowMax); v0.y = __expf(v0.y - rowMax);
        v0.z = __expf(v0.z - rowMax); v0.w = __expf(v0.w - rowMax);
        v1.x = __expf(v1.x - rowMax); v1.y = __expf(v1.y - rowMax);
        v1.z = __expf(v1.z - rowMax); v1.w = __expf(v1.w - rowMax);
        float sv = v0.x + v0.y + v0.z + v0.w + v1.x + v1.y + v1.z + v1.w;
        sv = warpSum(sv);
        if (lane == 0) red[wid] = sv;
        __syncthreads();
        if (wid == 0) {
            float t = (lane < 8) ? red[lane] : 0.f;
            t = warpSum(t);
            if (lane == 0) red[0] = t;
        }
        __syncthreads();
        const float inv = 1.f / red[0];
        __syncthreads();

        v0.x *= inv; v0.y *= inv; v0.z *= inv; v0.w *= inv;
        v1.x *= inv; v1.y *= inv; v1.z *= inv; v1.w *= inv;

        __nv_bfloat162* ph2 = (__nv_bfloat162*)(s_p_hi + rowoff);
        __nv_bfloat162* pl2 = (__nv_bfloat162*)(s_p_lo + rowoff);
        __nv_bfloat162 h0, h1, l0, l1;
        bsplit(v0.x, h0.x, l0.x); bsplit(v0.y, h0.y, l0.y);
        bsplit(v0.z, h1.x, l1.x); bsplit(v0.w, h1.y, l1.y);
        ph2[2*tid] = h0; ph2[2*tid+1] = h1;
        pl2[2*tid] = l0; pl2[2*tid+1] = l1;
        bsplit(v1.x, h0.x, l0.x); bsplit(v1.y, h0.y, l0.y);
        bsplit(v1.z, h1.x, l1.x); bsplit(v1.w, h1.y, l1.y);
        ph2[2*(tid+256)] = h0; ph2[2*(tid+256)+1] = h1;
        pl2[2*(tid+256)] = l0; pl2[2*(tid+256)+1] = l1;

        a0.x += v0.x; a0.y += v0.y; a0.z += v0.z; a0.w += v0.w;
        a1.x += v1.x; a1.y += v1.y; a1.z += v1.z; a1.w += v1.w;
    }

    const float invH = 1.f / NH;
    a0.x *= invH; a0.y *= invH; a0.z *= invH; a0.w *= invH;
    a1.x *= invH; a1.y *= invH; a1.z *= invH; a1.w *= invH;
    float4* o4 = (float4*)(avg + ((size_t)b * SEQ + q) * SEQ);
    o4[tid]       = a0;
    o4[tid + 256] = a1;
}

// ---------------- launch ----------------
extern "C" void kernel_launch(void* const* d_in, const int* in_sizes, int n_in,
                              void* d_out, int out_size)
{
    const float* query   = (const float*)d_in[0];
    const float* key     = (const float*)d_in[1];
    const float* value   = (const float*)d_in[2];
    const float* q_w     = (const float*)d_in[3];
    const float* q_b     = (const float*)d_in[4];
    const float* k_w     = (const float*)d_in[5];
    const float* k_b     = (const float*)d_in[6];
    const float* v_w     = (const float*)d_in[7];
    const float* v_b     = (const float*)d_in[8];
    const float* ow_mean = (const float*)d_in[9];
    const float* ow_lg   = (const float*)d_in[10];
    const float* eps     = (const float*)d_in[11];

    float* out_main = (float*)d_out;
    float* out_avg  = out_main + (size_t)MROWS * EMB;

    __nv_bfloat16 *xqh,*xql,*xkh,*xkl,*xvh,*xvl,*wqh,*wql,*wkh,*wkl,*wvh,*wvl;
    __nv_bfloat16 *owh,*owl,*qh,*ql,*kh,*kl,*vh,*vl,*pph,*ppl,*ch,*cl;
    float* attn_p;
    cudaGetSymbolAddress((void**)&xqh, s_xq_hi); cudaGetSymbolAddress((void**)&xql, s_xq_lo);
    cudaGetSymbolAddress((void**)&xkh, s_xk_hi); cudaGetSymbolAddress((void**)&xkl, s_xk_lo);
    cudaGetSymbolAddress((void**)&xvh, s_xv_hi); cudaGetSymbolAddress((void**)&xvl, s_xv_lo);
    cudaGetSymbolAddress((void**)&wqh, s_wq_hi); cudaGetSymbolAddress((void**)&wql, s_wq_lo);
    cudaGetSymbolAddress((void**)&wkh, s_wk_hi); cudaGetSymbolAddress((void**)&wkl, s_wk_lo);
    cudaGetSymbolAddress((void**)&wvh, s_wv_hi); cudaGetSymbolAddress((void**)&wvl, s_wv_lo);
    cudaGetSymbolAddress((void**)&owh, s_ow_hi); cudaGetSymbolAddress((void**)&owl, s_ow_lo);
    cudaGetSymbolAddress((void**)&qh,  s_q_hi);  cudaGetSymbolAddress((void**)&ql,  s_q_lo);
    cudaGetSymbolAddress((void**)&kh,  s_k_hi);  cudaGetSymbolAddress((void**)&kl,  s_k_lo);
    cudaGetSymbolAddress((void**)&vh,  s_v_hi);  cudaGetSymbolAddress((void**)&vl,  s_v_lo);
    cudaGetSymbolAddress((void**)&pph, s_p_hi);  cudaGetSymbolAddress((void**)&ppl, s_p_lo);
    cudaGetSymbolAddress((void**)&ch,  s_c_hi);  cudaGetSymbolAddress((void**)&cl,  s_c_lo);
    cudaGetSymbolAddress((void**)&attn_p, g_attn);

    // dynamic smem: 48 KB per CTA (2 CTAs/SM)
    const int SMEM = 2 * (2 * 128 * 64 + 2 * 64 * 64);
    cudaFuncSetAttribute(gemm_mma<0>, cudaFuncAttributeMaxDynamicSharedMemorySize, SMEM);
    cudaFuncSetAttribute(gemm_mma<1>, cudaFuncAttributeMaxDynamicSharedMemorySize, SMEM);
    cudaFuncSetAttribute(gemm_mma<2>, cudaFuncAttributeMaxDynamicSharedMemorySize, SMEM);
    cudaFuncSetAttribute(gemm_mma<3>, cudaFuncAttributeMaxDynamicSharedMemorySize, SMEM);

    // 1. fused split (launch #1), sampled output weight (launch #2)
    const int nx4 = MROWS * EMB / 4, nw4 = EMB * EMB / 4;
    {
        Split6Args a;
        a.src[0]=query; a.src[1]=key; a.src[2]=value;
        a.src[3]=q_w;   a.src[4]=k_w; a.src[5]=v_w;
        a.hi[0]=xqh; a.hi[1]=xkh; a.hi[2]=xvh; a.hi[3]=wqh; a.hi[4]=wkh; a.hi[5]=wvh;
        a.lo[0]=xql; a.lo[1]=xkl; a.lo[2]=xvl; a.lo[3]=wql; a.lo[4]=wkl; a.lo[5]=wvl;
        a.n4[0]=a.n4[1]=a.n4[2]=nx4; a.n4[3]=a.n4[4]=a.n4[5]=nw4;
        split6_kernel<<<dim3((nx4 + 255)/256, 6), 256>>>(a);
        ow_split_kernel<<<(nw4 + 255)/256, 256>>>(ow_mean, ow_lg, eps, nw4);
    }

    // 2. Q/K/V projections (launches #3,#4,#5)
    const dim3 gProj(EMB/64, MROWS/128, 1);
    gemm_mma<1><<<gProj, 256, SMEM>>>(xqh, xql, wqh, wql, EMB, EMB, EMB,
                                      0, 0, 0, nullptr, 0, qh, ql, q_b, 0.125f);
    gemm_mma<1><<<gProj, 256, SMEM>>>(xkh, xkl, wkh, wkl, EMB, EMB, EMB,
                                      0, 0, 0, nullptr, 0, kh, kl, k_b, 1.0f);
    gemm_mma<2><<<gProj, 256, SMEM>>>(xvh, xvl, wvh, wvl, EMB, EMB, EMB,
                                      0, 0, 0, nullptr, 0, vh, vl, v_b, 1.0f);

    // 3. scores = Q K^T (launch #6 — ncu -s 5 -c 1 captures this one)
    const dim3 gScore(SEQ/64, SEQ/128, BH);
    gemm_mma<0><<<gScore, 256, SMEM>>>(qh, ql, kh, kl, HD, HD, HD,
                                       (size_t)SEQ*HD, (size_t)SEQ*HD,
                                       (size_t)SEQ*SEQ, attn_p, SEQ,
                                       nullptr, nullptr, nullptr, 1.0f);

    // 4. softmax + avg + bf16 split of probs
    softmax_avg_kernel<<<BSZ*SEQ, 256>>>(attn_p, out_avg);

    // 5. ctx = P @ V  (batched; V stored [bh][d][s] -> NT form)
    const dim3 gCtx(1, SEQ/128, BH);
    gemm_mma<3><<<gCtx, 256, SMEM>>>(pph, ppl, vh, vl, SEQ, SEQ, SEQ,
                                     (size_t)SEQ*SEQ, (size_t)HD*SEQ, 0,
                                     nullptr, 0, ch, cl, nullptr, 1.0f);

    // 6. out = ctx @ o_w^T  (fp32 out)
    const dim3 gOut(EMB/64, MROWS/128, 1);
    gemm_mma<0><<<gOut, 256, SMEM>>>(ch, cl, owh, owl, EMB, EMB, EMB,
                                     0, 0, 0, out_main, EMB,
                                     nullptr, nullptr, nullptr, 1.0f);
}